// round 14
// baseline (speedup 1.0000x reference)
#include <cuda_runtime.h>

// ---------------------------------------------------------------------------
// SlayerNet forward, 2 real kernels (+2 empty dummies to steer ncu's
// skip-5/capture-1 window onto conv1_kernel next profile):
//   K1 conv1: x (64,100,2,32,32) -> conv(5x5,pad2)+sumpool4*p1 folded into an
//             effective 8x8/stride-4 kernel -> g_u1 [t][n*256+e]
//   K2 fused (512 threads), 4 barrier-separated parallel phases:
//     A: scan1 (PSP+refractory) per element, ALL t -> spike tile in SMEM
//     B: conv2eff for ALL t in parallel (t-stride 4) -> g_u2 (pre-scaled)
//     C: scan2 per element over t -> s2 spike bytes in SMEM
//     D: dense -> out (64,100,2)
// ---------------------------------------------------------------------------

#define TT   100
#define NB   64
#define NE1  16384   // 64 * 256 stage-1 elements (4,8,8)

// exp(-1/10) rounded to f32 (matches jnp f32 cast of np.exp(-0.1))
#define DECAY_F 0.9048374180359595f

// scratch (device globals: no allocations allowed)
__device__ float g_u1[TT * NE1];
__device__ float g_u2[NB * TT * 128];

// ---- packed f32x2 helpers (Blackwell FFMA2 path, PTX-only) ----------------
__device__ __forceinline__ unsigned long long pk2(float x) {
    unsigned int b = __float_as_uint(x);
    unsigned long long r;
    asm("mov.b64 %0, {%1, %1};" : "=l"(r) : "r"(b));
    return r;
}
__device__ __forceinline__ unsigned long long pack2(float lo, float hi) {
    unsigned long long r;
    asm("mov.b64 %0, {%1, %2};" : "=l"(r) : "r"(__float_as_uint(lo)), "r"(__float_as_uint(hi)));
    return r;
}
__device__ __forceinline__ void fma2(unsigned long long& acc,
                                     unsigned long long a,
                                     unsigned long long b) {
    asm("fma.rn.f32x2 %0, %1, %2, %0;" : "+l"(acc) : "l"(a), "l"(b));
}
__device__ __forceinline__ unsigned long long add2(unsigned long long a,
                                                   unsigned long long b) {
    unsigned long long r;
    asm("add.rn.f32x2 %0, %1, %2;" : "=l"(r) : "l"(a), "l"(b));
    return r;
}
__device__ __forceinline__ void unpk2(unsigned long long v, float& lo, float& hi) {
    unsigned int l, h;
    asm("mov.b64 {%0, %1}, %2;" : "=r"(l), "=r"(h) : "l"(v));
    lo = __uint_as_float(l);
    hi = __uint_as_float(h);
}

// empty kernel used only to position the ncu capture window
__global__ void dummy_kernel() {}

// ---------------------------------------------------------------------------
// K1: conv1eff per frame. One block = one (n,t) frame, 64 threads = 64 pooled
// windows. Round-13 changes: whole-frame register prefetch at entry (MLP=8,
// hidden under weight fold + halo fill), single __syncthreads.
// Compute loop and all arithmetic orders unchanged (rel_err 0.0 lineage).
// ---------------------------------------------------------------------------
__global__ __launch_bounds__(64) void conv1_kernel(const float* __restrict__ x,
                                                   const float* __restrict__ w1,
                                                   const float* __restrict__ pool1p) {
    __shared__ __align__(16) float sx[2 * 36 * 36];
    __shared__ float4 sw[128];  // [ci][u][v] -> (co0,co1,co2,co3)
    const int tid = threadIdx.x;
    const int f = blockIdx.x;
    const int n = f / 100, t = f - n * 100;

    // ---- prefetch the whole frame into registers (8 float4 per thread) ----
    const float4* xg = (const float4*)(x + (size_t)f * 2048);
    float4 rx[8];
    #pragma unroll
    for (int k = 0; k < 8; k++) rx[k] = xg[tid + 64 * k];

    // effective weights (identical arithmetic/order to the original fold)
    for (int i = tid; i < 128; i += 64) {
        int v = i & 7, u = (i >> 3) & 7, ci = i >> 6;
        int ky0 = max(0, u - 3), ky1 = min(4, u);
        int kx0 = max(0, v - 3), kx1 = min(4, v);
        float acc[4];
        #pragma unroll
        for (int co = 0; co < 4; co++) {
            float s = 0.f;
            for (int ky = ky0; ky <= ky1; ky++)
                for (int kx = kx0; kx <= kx1; kx++)
                    s += w1[((co * 2 + ci) * 5 + ky) * 5 + kx];
            acc[co] = s;
        }
        sw[i] = make_float4(acc[0], acc[1], acc[2], acc[3]);
    }

    // halo-only zero fill (disjoint from interior cells written below)
    for (int j = tid; j < 288; j += 64) {
        int ci = j / 144, rr = (j / 36) & 3, col = j % 36;
        int row = (rr < 2) ? rr : 32 + rr;
        sx[(ci * 36 + row) * 36 + col] = 0.f;
    }
    for (int j = tid; j < 256; j += 64) {
        int ci = j >> 7, r2 = (j >> 2) & 31, cc = j & 3;
        int col = (cc < 2) ? cc : 32 + cc;
        sx[(ci * 36 + 2 + r2) * 36 + col] = 0.f;
    }

    // ---- stage prefetched frame into the padded tile ----
    #pragma unroll
    for (int k = 0; k < 8; k++) {
        int i4 = tid + 64 * k;
        int ci = i4 >> 8, rem = i4 & 255, y = rem >> 3, xq = rem & 7;
        float* d = &sx[(ci * 36 + y + 2) * 36 + 4 * xq + 2];
        d[0] = rx[k].x; d[1] = rx[k].y; d[2] = rx[k].z; d[3] = rx[k].w;
    }
    __syncthreads();  // single barrier

    const int px = tid & 7, py = tid >> 3;
    unsigned long long acc01 = 0ull, acc23 = 0ull;
    #pragma unroll
    for (int ci = 0; ci < 2; ci++) {
        #pragma unroll
        for (int u = 0; u < 8; u++) {
            const float* row = &sx[(ci * 36 + py * 4 + u) * 36 + px * 4];
            float4 r0 = *(const float4*)row;
            float4 r1 = *(const float4*)(row + 4);
            float xv[8] = {r0.x, r0.y, r0.z, r0.w, r1.x, r1.y, r1.z, r1.w};
            #pragma unroll
            for (int v = 0; v < 8; v++) {
                const ulonglong2 w = *(const ulonglong2*)&sw[(ci * 8 + u) * 8 + v];
                unsigned long long xx = pk2(xv[v]);
                fma2(acc01, xx, w.x);
                fma2(acc23, xx, w.y);
            }
        }
    }
    const float p1 = *pool1p;
    float a0, a1, a2, a3;
    unpk2(acc01, a0, a1);
    unpk2(acc23, a2, a3);
    const int ob = t * NE1 + n * 256 + py * 8 + px;  // e = co*64 + py*8 + px
    g_u1[ob]       = a0 * p1;
    g_u1[ob + 64]  = a1 * p1;
    g_u1[ob + 128] = a2 * p1;
    g_u1[ob + 192] = a3 * p1;
}

// ---------------------------------------------------------------------------
// K2: fused, phase-parallel. grid=64 (one block per batch), 512 threads
// (16 warps -> 4/SMSP for latency hiding), ~202KB dynamic SMEM.
//   SMEM: tile  [100][4*10*12] float  (zero halo, left pad 3)   192000 B
//         slin  [256] float                                       1024 B
//         sw2   [288] float                                       1152 B
//         s2b   [100][128] bytes                                 12800 B
// ---------------------------------------------------------------------------
__global__ __launch_bounds__(512) void fused_kernel(const float* __restrict__ w2,
                                                    const float* __restrict__ lin,
                                                    const float* __restrict__ pool2p,
                                                    float* __restrict__ out) {
    extern __shared__ __align__(16) float smem[];
    float* tile = smem;                          // 48000 floats
    float* slin = smem + 48000;                  // 256
    float* sw2  = smem + 48256;                  // 288
    unsigned char* s2b = (unsigned char*)(smem + 48544);  // 12800 B

    const int tid = threadIdx.x;
    const int n = blockIdx.x;

    // ---- init: weights to SMEM, zero tile (halo cells stay 0 forever) ----
    for (int i = tid; i < 288; i += 512) sw2[i] = w2[i];
    if (tid < 256) slin[tid] = lin[tid];
    {
        float4* t4 = (float4*)tile;
        for (int i = tid; i < 12000; i += 512) t4[i] = make_float4(0.f, 0.f, 0.f, 0.f);
    }
    __syncthreads();

    // =========================================================================
    // Phase A: scan1 for all t. thread = stage-1 element e (first 256 threads).
    // u1 loads software-pipelined in groups of 10 (MLP=10) to hide L2 latency.
    // =========================================================================
    if (tid < 256) {
        const int e = tid;
        const int ci = e >> 6, y = (e >> 3) & 7, xx = e & 7;
        const int sofs = (ci * 10 + y + 1) * 12 + xx + 3;
        const float* up = g_u1 + n * 256 + e;

        float psp = 0.f, r = 0.f;
        float cur[10], nxt[10];
        #pragma unroll
        for (int k = 0; k < 10; k++) cur[k] = up[k * NE1];
        for (int tb = 0; tb < TT; tb += 10) {
            if (tb + 10 < TT) {
                #pragma unroll
                for (int k = 0; k < 10; k++) nxt[k] = up[(tb + 10 + k) * NE1];
            }
            #pragma unroll
            for (int k = 0; k < 10; k++) {
                psp = fmaf(DECAY_F, psp, cur[k]);
                float s = (psp - r >= 1.0f) ? 1.0f : 0.0f;
                r = DECAY_F * (r + s);
                tile[(tb + k) * 480 + sofs] = s;
            }
            #pragma unroll
            for (int k = 0; k < 10; k++) cur[k] = nxt[k];
        }
    }
    __syncthreads();

    // =========================================================================
    // Phase B: conv2eff for ALL t in parallel. 512 threads =
    //   tq = tid>>7 (t stride-4 phase), then h=ci-half, w=window, p=co-pair.
    // 25 independent iterations per thread; 4 accumulators (by row u).
    // Output u2 (pre-scaled by p2) -> g_u2[(n*100+t)*128 + e2].
    // =========================================================================
    {
        const int tq = tid >> 7;       // 0..3
        const int q  = tid & 127;
        const int h  = q & 1;          // ci half: {0,1} or {2,3}
        const int w  = (q >> 1) & 15;  // window 0..15
        const int p  = q >> 5;         // co-pair 0..3
        const int py = w >> 2, px = w & 3;

        // per-thread effective conv2 weights (same fold math/order as before)
        unsigned long long wreg[2][4][4];
        #pragma unroll
        for (int cl = 0; cl < 2; cl++) {
            int ci = 2 * h + cl;
            #pragma unroll
            for (int u = 0; u < 4; u++) {
                #pragma unroll
                for (int v = 0; v < 4; v++) {
                    int ky0 = max(0, u - 1), ky1 = min(2, u);
                    int kx0 = max(0, v - 1), kx1 = min(2, v);
                    float s0 = 0.f, s1 = 0.f;
                    for (int ky = ky0; ky <= ky1; ky++)
                        for (int kx = kx0; kx <= kx1; kx++) {
                            s0 += sw2[((2 * p)     * 4 + ci) * 9 + ky * 3 + kx];
                            s1 += sw2[((2 * p + 1) * 4 + ci) * 9 + ky * 3 + kx];
                        }
                    wreg[cl][u][v] = pack2(s0, s1);
                }
            }
        }
        const float p2 = *pool2p;
        const int e2a = 32 * p + w;   // co = 2p
        const int rofs = (2 * h * 10 + py * 2) * 12 + px * 2 + 2;
        float* u2base = g_u2 + (size_t)n * TT * 128;

        for (int t = tq; t < TT; t += 4) {
            const float* tb = &tile[t * 480 + rofs];
            unsigned long long a0 = 0ull, a1 = 0ull, a2 = 0ull, a3 = 0ull;
            #pragma unroll
            for (int cl = 0; cl < 2; cl++) {
                #pragma unroll
                for (int u = 0; u < 4; u++) {
                    const float* row = tb + (cl * 10 + u) * 12;
                    float2 q0 = *(const float2*)row;
                    float2 q1 = *(const float2*)(row + 2);
                    unsigned long long* acc =
                        (u == 0) ? &a0 : (u == 1) ? &a1 : (u == 2) ? &a2 : &a3;
                    fma2(*acc, pk2(q0.x), wreg[cl][u][0]);
                    fma2(*acc, pk2(q0.y), wreg[cl][u][1]);
                    fma2(*acc, pk2(q1.x), wreg[cl][u][2]);
                    fma2(*acc, pk2(q1.y), wreg[cl][u][3]);
                }
            }
            unsigned long long acc = add2(add2(a0, a1), add2(a2, a3));
            // combine ci halves: lane pairs (even h=0, odd h=1)
            unsigned long long accO = __shfl_down_sync(0xffffffffu, acc, 1);
            if (h == 0) {
                float A0, A1, B0, B1;
                unpk2(acc, A0, A1);
                unpk2(accO, B0, B1);
                u2base[t * 128 + e2a]      = (A0 + B0) * p2;
                u2base[t * 128 + e2a + 16] = (A1 + B1) * p2;
            }
        }
    }
    __syncthreads();  // also orders g_u2 writes vs reads within the block

    // =========================================================================
    // Phase C: scan2. thread = stage-2 element e (128 threads), pipelined
    // u2 loads, s2 spikes stored as bytes in SMEM.
    // =========================================================================
    if (tid < 128) {
        const int e = tid;
        const float* up = g_u2 + (size_t)n * TT * 128 + e;
        float psp = 0.f, r = 0.f;
        float cur[10], nxt[10];
        #pragma unroll
        for (int k = 0; k < 10; k++) cur[k] = up[k * 128];
        for (int tb = 0; tb < TT; tb += 10) {
            if (tb + 10 < TT) {
                #pragma unroll
                for (int k = 0; k < 10; k++) nxt[k] = up[(tb + 10 + k) * 128];
            }
            #pragma unroll
            for (int k = 0; k < 10; k++) {
                psp = fmaf(DECAY_F, psp, cur[k]);
                float s = (psp - r >= 1.0f) ? 1.0f : 0.0f;
                r = DECAY_F * (r + s);
                s2b[(tb + k) * 128 + e] = (unsigned char)(s != 0.f);
            }
            #pragma unroll
            for (int k = 0; k < 10; k++) cur[k] = nxt[k];
        }
    }
    __syncthreads();

    // =========================================================================
    // Phase D: dense layer, thread = timestep.
    // =========================================================================
    if (tid < TT) {
        const unsigned char* row = &s2b[tid * 128];
        float o0 = 0.f, o1 = 0.f;
        #pragma unroll 16
        for (int e = 0; e < 128; e++) {
            float s = (float)row[e];
            o0 = fmaf(s, slin[e], o0);
            o1 = fmaf(s, slin[128 + e], o1);
        }
        out[n * 200 + tid * 2]     = o0;
        out[n * 200 + tid * 2 + 1] = o1;
    }
}

// ---------------------------------------------------------------------------
#define FUSED_SMEM 206976  // 48544 floats + 12800 bytes

extern "C" void kernel_launch(void* const* d_in, const int* in_sizes, int n_in,
                              void* d_out, int out_size) {
    const float* x   = (const float*)d_in[0];  // (64,100,2,32,32)
    const float* w1  = (const float*)d_in[1];  // (4,2,5,5)
    const float* w2  = (const float*)d_in[2];  // (8,4,3,3)
    const float* lin = (const float*)d_in[3];  // (2,8,4,4)
    const float* p1  = (const float*)d_in[4];  // scalar
    const float* p2  = (const float*)d_in[5];  // scalar
    float* out = (float*)d_out;                // (64,100,2)

    cudaFuncSetAttribute(fused_kernel,
                         cudaFuncAttributeMaxDynamicSharedMemorySize, FUSED_SMEM);
    // 4-launch pattern (dummy, conv1, fused, dummy): positions ncu's
    // skip-5/capture-1 window on conv1_kernel (launch #6) next profile.
    dummy_kernel<<<1, 32>>>();
    conv1_kernel<<<NB * TT, 64>>>(x, w1, p1);
    fused_kernel<<<NB, 512, FUSED_SMEM>>>(w2, lin, p2, out);
    dummy_kernel<<<1, 32>>>();
}

// round 15
// speedup vs baseline: 1.0005x; 1.0005x over previous
#include <cuda_runtime.h>

// ---------------------------------------------------------------------------
// SlayerNet forward:
//   K1 conv1 (x2 half-grids): x -> conv(5x5,pad2)+sumpool4*p1 folded into an
//        effective 8x8/stride-4 kernel -> g_u1 [t][n*256+e].
//        4 frames per 256-thread block.
//   K2 fused (512 threads), 4 barrier-separated parallel phases:
//     A: scan1 (PSP+refractory) per element, ALL t -> spike tile in SMEM
//     B: conv2eff for ALL t in parallel (t-stride 4) -> g_u2 (pre-scaled)
//     C: scan2 per element over t -> s2 spike bytes in SMEM
//     D: dense -> out (64,100,2)
//   K3 conv1 tiny re-run (148 blocks, idempotent): exists ONLY so the ncu
//        capture window (empirically: 4th launch) lands on conv1 code.
// ---------------------------------------------------------------------------

#define TT   100
#define NB   64
#define NE1  16384   // 64 * 256 stage-1 elements (4,8,8)

// exp(-1/10) rounded to f32 (matches jnp f32 cast of np.exp(-0.1))
#define DECAY_F 0.9048374180359595f

// scratch (device globals: no allocations allowed)
__device__ float g_u1[TT * NE1];
__device__ float g_u2[NB * TT * 128];

// ---- packed f32x2 helpers (Blackwell FFMA2 path, PTX-only) ----------------
__device__ __forceinline__ unsigned long long pk2(float x) {
    unsigned int b = __float_as_uint(x);
    unsigned long long r;
    asm("mov.b64 %0, {%1, %1};" : "=l"(r) : "r"(b));
    return r;
}
__device__ __forceinline__ unsigned long long pack2(float lo, float hi) {
    unsigned long long r;
    asm("mov.b64 %0, {%1, %2};" : "=l"(r) : "r"(__float_as_uint(lo)), "r"(__float_as_uint(hi)));
    return r;
}
__device__ __forceinline__ void fma2(unsigned long long& acc,
                                     unsigned long long a,
                                     unsigned long long b) {
    asm("fma.rn.f32x2 %0, %1, %2, %0;" : "+l"(acc) : "l"(a), "l"(b));
}
__device__ __forceinline__ unsigned long long add2(unsigned long long a,
                                                   unsigned long long b) {
    unsigned long long r;
    asm("add.rn.f32x2 %0, %1, %2;" : "=l"(r) : "l"(a), "l"(b));
    return r;
}
__device__ __forceinline__ void unpk2(unsigned long long v, float& lo, float& hi) {
    unsigned int l, h;
    asm("mov.b64 {%0, %1}, %2;" : "=r"(l), "=r"(h) : "l"(v));
    lo = __uint_as_float(l);
    hi = __uint_as_float(h);
}

// ---------------------------------------------------------------------------
// K1: conv1eff, 4 frames per 256-thread block. Group g = tid>>6 owns frame
// base + 4*blockIdx.x + g; lid = tid&63 is the pooled-window index within the
// frame. Weight fold done once per block (shared by the 4 frames). The
// staging, halo fill, compute loop and all arithmetic orders are unchanged
// from the passing rounds (rel_err 0.0 lineage).
// ---------------------------------------------------------------------------
__global__ __launch_bounds__(256) void conv1_kernel(const float* __restrict__ x,
                                                    const float* __restrict__ w1,
                                                    const float* __restrict__ pool1p,
                                                    int frame_base) {
    __shared__ __align__(16) float sx[4][2 * 36 * 36];  // 4 x 10.4KB
    __shared__ float4 sw[128];  // [ci][u][v] -> (co0,co1,co2,co3)
    const int tid = threadIdx.x;
    const int g   = tid >> 6;        // frame group 0..3
    const int lid = tid & 63;        // window index within frame
    const int f = frame_base + blockIdx.x * 4 + g;
    const int n = f / 100, t = f - n * 100;
    float* sxf = sx[g];

    // ---- prefetch this group's frame into registers (8 float4/thread) ----
    const float4* xg = (const float4*)(x + (size_t)f * 2048);
    float4 rx[8];
    #pragma unroll
    for (int k = 0; k < 8; k++) rx[k] = xg[lid + 64 * k];

    // effective weights, once per block (identical fold math/order)
    if (tid < 128) {
        int i = tid;
        int v = i & 7, u = (i >> 3) & 7, ci = i >> 6;
        int ky0 = max(0, u - 3), ky1 = min(4, u);
        int kx0 = max(0, v - 3), kx1 = min(4, v);
        float acc[4];
        #pragma unroll
        for (int co = 0; co < 4; co++) {
            float s = 0.f;
            for (int ky = ky0; ky <= ky1; ky++)
                for (int kx = kx0; kx <= kx1; kx++)
                    s += w1[((co * 2 + ci) * 5 + ky) * 5 + kx];
            acc[co] = s;
        }
        sw[i] = make_float4(acc[0], acc[1], acc[2], acc[3]);
    }

    // halo-only zero fill (disjoint from interior cells written below)
    for (int j = lid; j < 288; j += 64) {
        int ci = j / 144, rr = (j / 36) & 3, col = j % 36;
        int row = (rr < 2) ? rr : 32 + rr;
        sxf[(ci * 36 + row) * 36 + col] = 0.f;
    }
    for (int j = lid; j < 256; j += 64) {
        int ci = j >> 7, r2 = (j >> 2) & 31, cc = j & 3;
        int col = (cc < 2) ? cc : 32 + cc;
        sxf[(ci * 36 + 2 + r2) * 36 + col] = 0.f;
    }

    // ---- stage prefetched frame into the padded tile ----
    #pragma unroll
    for (int k = 0; k < 8; k++) {
        int i4 = lid + 64 * k;
        int ci = i4 >> 8, rem = i4 & 255, y = rem >> 3, xq = rem & 7;
        float* d = &sxf[(ci * 36 + y + 2) * 36 + 4 * xq + 2];
        d[0] = rx[k].x; d[1] = rx[k].y; d[2] = rx[k].z; d[3] = rx[k].w;
    }
    __syncthreads();  // single barrier

    const int px = lid & 7, py = lid >> 3;
    unsigned long long acc01 = 0ull, acc23 = 0ull;
    #pragma unroll
    for (int ci = 0; ci < 2; ci++) {
        #pragma unroll
        for (int u = 0; u < 8; u++) {
            const float* row = &sxf[(ci * 36 + py * 4 + u) * 36 + px * 4];
            float4 r0 = *(const float4*)row;
            float4 r1 = *(const float4*)(row + 4);
            float xv[8] = {r0.x, r0.y, r0.z, r0.w, r1.x, r1.y, r1.z, r1.w};
            #pragma unroll
            for (int v = 0; v < 8; v++) {
                const ulonglong2 w = *(const ulonglong2*)&sw[(ci * 8 + u) * 8 + v];
                unsigned long long xx = pk2(xv[v]);
                fma2(acc01, xx, w.x);
                fma2(acc23, xx, w.y);
            }
        }
    }
    const float p1 = *pool1p;
    float a0, a1, a2, a3;
    unpk2(acc01, a0, a1);
    unpk2(acc23, a2, a3);
    const int ob = t * NE1 + n * 256 + py * 8 + px;  // e = co*64 + py*8 + px
    g_u1[ob]       = a0 * p1;
    g_u1[ob + 64]  = a1 * p1;
    g_u1[ob + 128] = a2 * p1;
    g_u1[ob + 192] = a3 * p1;
}

// ---------------------------------------------------------------------------
// K2: fused, phase-parallel. grid=64 (one block per batch), 512 threads,
// ~202KB dynamic SMEM. Unchanged from round 14.
// ---------------------------------------------------------------------------
__global__ __launch_bounds__(512) void fused_kernel(const float* __restrict__ w2,
                                                    const float* __restrict__ lin,
                                                    const float* __restrict__ pool2p,
                                                    float* __restrict__ out) {
    extern __shared__ __align__(16) float smem[];
    float* tile = smem;                          // 48000 floats
    float* slin = smem + 48000;                  // 256
    float* sw2  = smem + 48256;                  // 288
    unsigned char* s2b = (unsigned char*)(smem + 48544);  // 12800 B

    const int tid = threadIdx.x;
    const int n = blockIdx.x;

    for (int i = tid; i < 288; i += 512) sw2[i] = w2[i];
    if (tid < 256) slin[tid] = lin[tid];
    {
        float4* t4 = (float4*)tile;
        for (int i = tid; i < 12000; i += 512) t4[i] = make_float4(0.f, 0.f, 0.f, 0.f);
    }
    __syncthreads();

    // ---- Phase A: scan1 for all t (256 threads, MLP-10 pipelined loads) ----
    if (tid < 256) {
        const int e = tid;
        const int ci = e >> 6, y = (e >> 3) & 7, xx = e & 7;
        const int sofs = (ci * 10 + y + 1) * 12 + xx + 3;
        const float* up = g_u1 + n * 256 + e;

        float psp = 0.f, r = 0.f;
        float cur[10], nxt[10];
        #pragma unroll
        for (int k = 0; k < 10; k++) cur[k] = up[k * NE1];
        for (int tb = 0; tb < TT; tb += 10) {
            if (tb + 10 < TT) {
                #pragma unroll
                for (int k = 0; k < 10; k++) nxt[k] = up[(tb + 10 + k) * NE1];
            }
            #pragma unroll
            for (int k = 0; k < 10; k++) {
                psp = fmaf(DECAY_F, psp, cur[k]);
                float s = (psp - r >= 1.0f) ? 1.0f : 0.0f;
                r = DECAY_F * (r + s);
                tile[(tb + k) * 480 + sofs] = s;
            }
            #pragma unroll
            for (int k = 0; k < 10; k++) cur[k] = nxt[k];
        }
    }
    __syncthreads();

    // ---- Phase B: conv2eff for all t (512 threads, t-stride 4) ----
    {
        const int tq = tid >> 7;       // 0..3
        const int q  = tid & 127;
        const int h  = q & 1;          // ci half
        const int w  = (q >> 1) & 15;  // window
        const int p  = q >> 5;         // co-pair
        const int py = w >> 2, px = w & 3;

        unsigned long long wreg[2][4][4];
        #pragma unroll
        for (int cl = 0; cl < 2; cl++) {
            int ci = 2 * h + cl;
            #pragma unroll
            for (int u = 0; u < 4; u++) {
                #pragma unroll
                for (int v = 0; v < 4; v++) {
                    int ky0 = max(0, u - 1), ky1 = min(2, u);
                    int kx0 = max(0, v - 1), kx1 = min(2, v);
                    float s0 = 0.f, s1 = 0.f;
                    for (int ky = ky0; ky <= ky1; ky++)
                        for (int kx = kx0; kx <= kx1; kx++) {
                            s0 += sw2[((2 * p)     * 4 + ci) * 9 + ky * 3 + kx];
                            s1 += sw2[((2 * p + 1) * 4 + ci) * 9 + ky * 3 + kx];
                        }
                    wreg[cl][u][v] = pack2(s0, s1);
                }
            }
        }
        const float p2 = *pool2p;
        const int e2a = 32 * p + w;
        const int rofs = (2 * h * 10 + py * 2) * 12 + px * 2 + 2;
        float* u2base = g_u2 + (size_t)n * TT * 128;

        for (int t = tq; t < TT; t += 4) {
            const float* tb = &tile[t * 480 + rofs];
            unsigned long long a0 = 0ull, a1 = 0ull, a2 = 0ull, a3 = 0ull;
            #pragma unroll
            for (int cl = 0; cl < 2; cl++) {
                #pragma unroll
                for (int u = 0; u < 4; u++) {
                    const float* row = tb + (cl * 10 + u) * 12;
                    float2 q0 = *(const float2*)row;
                    float2 q1 = *(const float2*)(row + 2);
                    unsigned long long* acc =
                        (u == 0) ? &a0 : (u == 1) ? &a1 : (u == 2) ? &a2 : &a3;
                    fma2(*acc, pk2(q0.x), wreg[cl][u][0]);
                    fma2(*acc, pk2(q0.y), wreg[cl][u][1]);
                    fma2(*acc, pk2(q1.x), wreg[cl][u][2]);
                    fma2(*acc, pk2(q1.y), wreg[cl][u][3]);
                }
            }
            unsigned long long acc = add2(add2(a0, a1), add2(a2, a3));
            unsigned long long accO = __shfl_down_sync(0xffffffffu, acc, 1);
            if (h == 0) {
                float A0, A1, B0, B1;
                unpk2(acc, A0, A1);
                unpk2(accO, B0, B1);
                u2base[t * 128 + e2a]      = (A0 + B0) * p2;
                u2base[t * 128 + e2a + 16] = (A1 + B1) * p2;
            }
        }
    }
    __syncthreads();

    // ---- Phase C: scan2 (128 threads, pipelined) ----
    if (tid < 128) {
        const int e = tid;
        const float* up = g_u2 + (size_t)n * TT * 128 + e;
        float psp = 0.f, r = 0.f;
        float cur[10], nxt[10];
        #pragma unroll
        for (int k = 0; k < 10; k++) cur[k] = up[k * 128];
        for (int tb = 0; tb < TT; tb += 10) {
            if (tb + 10 < TT) {
                #pragma unroll
                for (int k = 0; k < 10; k++) nxt[k] = up[(tb + 10 + k) * 128];
            }
            #pragma unroll
            for (int k = 0; k < 10; k++) {
                psp = fmaf(DECAY_F, psp, cur[k]);
                float s = (psp - r >= 1.0f) ? 1.0f : 0.0f;
                r = DECAY_F * (r + s);
                s2b[(tb + k) * 128 + e] = (unsigned char)(s != 0.f);
            }
            #pragma unroll
            for (int k = 0; k < 10; k++) cur[k] = nxt[k];
        }
    }
    __syncthreads();

    // ---- Phase D: dense layer, thread = timestep ----
    if (tid < TT) {
        const unsigned char* row = &s2b[tid * 128];
        float o0 = 0.f, o1 = 0.f;
        #pragma unroll 16
        for (int e = 0; e < 128; e++) {
            float s = (float)row[e];
            o0 = fmaf(s, slin[e], o0);
            o1 = fmaf(s, slin[128 + e], o1);
        }
        out[n * 200 + tid * 2]     = o0;
        out[n * 200 + tid * 2 + 1] = o1;
    }
}

// ---------------------------------------------------------------------------
#define FUSED_SMEM 206976  // 48544 floats + 12800 bytes

extern "C" void kernel_launch(void* const* d_in, const int* in_sizes, int n_in,
                              void* d_out, int out_size) {
    const float* x   = (const float*)d_in[0];  // (64,100,2,32,32)
    const float* w1  = (const float*)d_in[1];  // (4,2,5,5)
    const float* w2  = (const float*)d_in[2];  // (8,4,3,3)
    const float* lin = (const float*)d_in[3];  // (2,8,4,4)
    const float* p1  = (const float*)d_in[4];  // scalar
    const float* p2  = (const float*)d_in[5];  // scalar
    float* out = (float*)d_out;                // (64,100,2)

    cudaFuncSetAttribute(fused_kernel,
                         cudaFuncAttributeMaxDynamicSharedMemorySize, FUSED_SMEM);

    // 4 launches; the 4th (empirically the ncu-captured one) is a cheap
    // IDEMPOTENT conv1 re-run on one wave, so next profile shows conv1.
    conv1_kernel<<<800, 256>>>(x, w1, p1, 0);     // frames    0..3199
    conv1_kernel<<<800, 256>>>(x, w1, p1, 3200);  // frames 3200..6399
    fused_kernel<<<NB, 512, FUSED_SMEM>>>(w2, lin, p2, out);
    conv1_kernel<<<148, 256>>>(x, w1, p1, 0);     // profiling target (idempotent)
}

// round 16
// speedup vs baseline: 1.3181x; 1.3175x over previous
#include <cuda_runtime.h>

// ---------------------------------------------------------------------------
// SlayerNet forward:
//   K0 prep  : fold conv1 (5x5 + sumpool4) into effective 8x8/stride-4
//              weights ONCE -> g_w1eff. (Previously re-folded per conv1 block
//              via ~25 serialized global loads = the dominant latency cost.)
//   K1 conv1 (x2 half-grids): x -> conv1eff -> g_u1 [t][n*256+e],
//              4 frames per 256-thread block.
//   K2 fused (512 threads), 4 barrier-separated parallel phases:
//     A: scan1 (PSP+refractory) per element, ALL t -> spike tile in SMEM
//     B: conv2eff for ALL t in parallel (t-stride 4) -> g_u2 (pre-scaled)
//     C: scan2 per element over t -> s2 spike bytes in SMEM
//     D: dense -> out (64,100,2)
//   Fused tile stride = 484 floats (≡4 mod 32 banks) so phase-B threads that
//   differ only in t no longer 4-way bank-conflict (480 ≡ 0 mod 32 did).
// ---------------------------------------------------------------------------

#define TT   100
#define NB   64
#define NE1  16384   // 64 * 256 stage-1 elements (4,8,8)
#define TSTR 484     // fused spike-tile stride in floats (was 480)

// exp(-1/10) rounded to f32 (matches jnp f32 cast of np.exp(-0.1))
#define DECAY_F 0.9048374180359595f

// scratch (device globals: no allocations allowed)
__device__ float  g_u1[TT * NE1];
__device__ float  g_u2[NB * TT * 128];
__device__ float4 g_w1eff[128];   // [ci][u][v] -> (co0,co1,co2,co3)

// ---- packed f32x2 helpers (Blackwell FFMA2 path, PTX-only) ----------------
__device__ __forceinline__ unsigned long long pk2(float x) {
    unsigned int b = __float_as_uint(x);
    unsigned long long r;
    asm("mov.b64 %0, {%1, %1};" : "=l"(r) : "r"(b));
    return r;
}
__device__ __forceinline__ unsigned long long pack2(float lo, float hi) {
    unsigned long long r;
    asm("mov.b64 %0, {%1, %2};" : "=l"(r) : "r"(__float_as_uint(lo)), "r"(__float_as_uint(hi)));
    return r;
}
__device__ __forceinline__ void fma2(unsigned long long& acc,
                                     unsigned long long a,
                                     unsigned long long b) {
    asm("fma.rn.f32x2 %0, %1, %2, %0;" : "+l"(acc) : "l"(a), "l"(b));
}
__device__ __forceinline__ unsigned long long add2(unsigned long long a,
                                                   unsigned long long b) {
    unsigned long long r;
    asm("add.rn.f32x2 %0, %1, %2;" : "=l"(r) : "l"(a), "l"(b));
    return r;
}
__device__ __forceinline__ void unpk2(unsigned long long v, float& lo, float& hi) {
    unsigned int l, h;
    asm("mov.b64 {%0, %1}, %2;" : "=r"(l), "=r"(h) : "l"(v));
    lo = __uint_as_float(l);
    hi = __uint_as_float(h);
}

// ---------------------------------------------------------------------------
// K0: one-block prep — fold conv1+pool into g_w1eff. Arithmetic and summation
// order identical to the previous in-block fold (rel_err 0.0 lineage).
// ---------------------------------------------------------------------------
__global__ void prep_kernel(const float* __restrict__ w1) {
    int i = threadIdx.x;  // 128 threads
    int v = i & 7, u = (i >> 3) & 7, ci = i >> 6;
    int ky0 = max(0, u - 3), ky1 = min(4, u);
    int kx0 = max(0, v - 3), kx1 = min(4, v);
    float acc[4];
    #pragma unroll
    for (int co = 0; co < 4; co++) {
        float s = 0.f;
        for (int ky = ky0; ky <= ky1; ky++)
            for (int kx = kx0; kx <= kx1; kx++)
                s += w1[((co * 2 + ci) * 5 + ky) * 5 + kx];
        acc[co] = s;
    }
    g_w1eff[i] = make_float4(acc[0], acc[1], acc[2], acc[3]);
}

// ---------------------------------------------------------------------------
// K1: conv1eff, 4 frames per 256-thread block. Group g = tid>>6 owns frame
// base + 4*blockIdx.x + g; lid = tid&63 is the pooled-window index. Effective
// weights now LOADED (128 float4, coalesced) instead of re-folded per block.
// Staging, halo fill, compute loop, arithmetic orders unchanged.
// ---------------------------------------------------------------------------
__global__ __launch_bounds__(256) void conv1_kernel(const float* __restrict__ x,
                                                    const float* __restrict__ pool1p,
                                                    int frame_base) {
    __shared__ __align__(16) float sx[4][2 * 36 * 36];  // 4 x 10.4KB
    __shared__ float4 sw[128];
    const int tid = threadIdx.x;
    const int g   = tid >> 6;        // frame group 0..3
    const int lid = tid & 63;        // window index within frame
    const int f = frame_base + blockIdx.x * 4 + g;
    const int n = f / 100, t = f - n * 100;
    float* sxf = sx[g];

    // ---- prefetch this group's frame into registers (8 float4/thread) ----
    const float4* xg = (const float4*)(x + (size_t)f * 2048);
    float4 rx[8];
    #pragma unroll
    for (int k = 0; k < 8; k++) rx[k] = xg[lid + 64 * k];

    // effective weights: one coalesced float4 load per thread (tid<128)
    if (tid < 128) sw[tid] = g_w1eff[tid];

    // halo-only zero fill (disjoint from interior cells written below)
    for (int j = lid; j < 288; j += 64) {
        int ci = j / 144, rr = (j / 36) & 3, col = j % 36;
        int row = (rr < 2) ? rr : 32 + rr;
        sxf[(ci * 36 + row) * 36 + col] = 0.f;
    }
    for (int j = lid; j < 256; j += 64) {
        int ci = j >> 7, r2 = (j >> 2) & 31, cc = j & 3;
        int col = (cc < 2) ? cc : 32 + cc;
        sxf[(ci * 36 + 2 + r2) * 36 + col] = 0.f;
    }

    // ---- stage prefetched frame into the padded tile ----
    #pragma unroll
    for (int k = 0; k < 8; k++) {
        int i4 = lid + 64 * k;
        int ci = i4 >> 8, rem = i4 & 255, y = rem >> 3, xq = rem & 7;
        float* d = &sxf[(ci * 36 + y + 2) * 36 + 4 * xq + 2];
        d[0] = rx[k].x; d[1] = rx[k].y; d[2] = rx[k].z; d[3] = rx[k].w;
    }
    __syncthreads();  // single barrier

    const int px = lid & 7, py = lid >> 3;
    unsigned long long acc01 = 0ull, acc23 = 0ull;
    #pragma unroll
    for (int ci = 0; ci < 2; ci++) {
        #pragma unroll
        for (int u = 0; u < 8; u++) {
            const float* row = &sxf[(ci * 36 + py * 4 + u) * 36 + px * 4];
            float4 r0 = *(const float4*)row;
            float4 r1 = *(const float4*)(row + 4);
            float xv[8] = {r0.x, r0.y, r0.z, r0.w, r1.x, r1.y, r1.z, r1.w};
            #pragma unroll
            for (int v = 0; v < 8; v++) {
                const ulonglong2 w = *(const ulonglong2*)&sw[(ci * 8 + u) * 8 + v];
                unsigned long long xx = pk2(xv[v]);
                fma2(acc01, xx, w.x);
                fma2(acc23, xx, w.y);
            }
        }
    }
    const float p1 = *pool1p;
    float a0, a1, a2, a3;
    unpk2(acc01, a0, a1);
    unpk2(acc23, a2, a3);
    const int ob = t * NE1 + n * 256 + py * 8 + px;  // e = co*64 + py*8 + px
    g_u1[ob]       = a0 * p1;
    g_u1[ob + 64]  = a1 * p1;
    g_u1[ob + 128] = a2 * p1;
    g_u1[ob + 192] = a3 * p1;
}

// ---------------------------------------------------------------------------
// K2: fused, phase-parallel. grid=64 (one block per batch), 512 threads,
// ~204KB dynamic SMEM. Tile stride 484 (bank-spread); otherwise unchanged.
//   SMEM: tile  [100][TSTR] float                               193600 B
//         slin  [256] float                                       1024 B
//         sw2   [288] float                                       1152 B
//         s2b   [100][128] bytes                                 12800 B
// ---------------------------------------------------------------------------
__global__ __launch_bounds__(512) void fused_kernel(const float* __restrict__ w2,
                                                    const float* __restrict__ lin,
                                                    const float* __restrict__ pool2p,
                                                    float* __restrict__ out) {
    extern __shared__ __align__(16) float smem[];
    float* tile = smem;                                   // TT*TSTR floats
    float* slin = smem + TT * TSTR;                       // 256
    float* sw2  = smem + TT * TSTR + 256;                 // 288
    unsigned char* s2b = (unsigned char*)(smem + TT * TSTR + 544);  // 12800 B

    const int tid = threadIdx.x;
    const int n = blockIdx.x;

    for (int i = tid; i < 288; i += 512) sw2[i] = w2[i];
    if (tid < 256) slin[tid] = lin[tid];
    {
        float4* t4 = (float4*)tile;
        for (int i = tid; i < TT * TSTR / 4; i += 512)
            t4[i] = make_float4(0.f, 0.f, 0.f, 0.f);
    }
    __syncthreads();

    // ---- Phase A: scan1 for all t (256 threads, MLP-10 pipelined loads) ----
    if (tid < 256) {
        const int e = tid;
        const int ci = e >> 6, y = (e >> 3) & 7, xx = e & 7;
        const int sofs = (ci * 10 + y + 1) * 12 + xx + 3;
        const float* up = g_u1 + n * 256 + e;

        float psp = 0.f, r = 0.f;
        float cur[10], nxt[10];
        #pragma unroll
        for (int k = 0; k < 10; k++) cur[k] = up[k * NE1];
        for (int tb = 0; tb < TT; tb += 10) {
            if (tb + 10 < TT) {
                #pragma unroll
                for (int k = 0; k < 10; k++) nxt[k] = up[(tb + 10 + k) * NE1];
            }
            #pragma unroll
            for (int k = 0; k < 10; k++) {
                psp = fmaf(DECAY_F, psp, cur[k]);
                float s = (psp - r >= 1.0f) ? 1.0f : 0.0f;
                r = DECAY_F * (r + s);
                tile[(tb + k) * TSTR + sofs] = s;
            }
            #pragma unroll
            for (int k = 0; k < 10; k++) cur[k] = nxt[k];
        }
    }
    __syncthreads();

    // ---- Phase B: conv2eff for all t (512 threads, t-stride 4) ----
    {
        const int tq = tid >> 7;       // 0..3
        const int q  = tid & 127;
        const int h  = q & 1;          // ci half
        const int w  = (q >> 1) & 15;  // window
        const int p  = q >> 5;         // co-pair
        const int py = w >> 2, px = w & 3;

        unsigned long long wreg[2][4][4];
        #pragma unroll
        for (int cl = 0; cl < 2; cl++) {
            int ci = 2 * h + cl;
            #pragma unroll
            for (int u = 0; u < 4; u++) {
                #pragma unroll
                for (int v = 0; v < 4; v++) {
                    int ky0 = max(0, u - 1), ky1 = min(2, u);
                    int kx0 = max(0, v - 1), kx1 = min(2, v);
                    float s0 = 0.f, s1 = 0.f;
                    for (int ky = ky0; ky <= ky1; ky++)
                        for (int kx = kx0; kx <= kx1; kx++) {
                            s0 += sw2[((2 * p)     * 4 + ci) * 9 + ky * 3 + kx];
                            s1 += sw2[((2 * p + 1) * 4 + ci) * 9 + ky * 3 + kx];
                        }
                    wreg[cl][u][v] = pack2(s0, s1);
                }
            }
        }
        const float p2 = *pool2p;
        const int e2a = 32 * p + w;
        const int rofs = (2 * h * 10 + py * 2) * 12 + px * 2 + 2;
        float* u2base = g_u2 + (size_t)n * TT * 128;

        for (int t = tq; t < TT; t += 4) {
            const float* tb = &tile[t * TSTR + rofs];
            unsigned long long a0 = 0ull, a1 = 0ull, a2 = 0ull, a3 = 0ull;
            #pragma unroll
            for (int cl = 0; cl < 2; cl++) {
                #pragma unroll
                for (int u = 0; u < 4; u++) {
                    const float* row = tb + (cl * 10 + u) * 12;
                    float2 q0 = *(const float2*)row;
                    float2 q1 = *(const float2*)(row + 2);
                    unsigned long long* acc =
                        (u == 0) ? &a0 : (u == 1) ? &a1 : (u == 2) ? &a2 : &a3;
                    fma2(*acc, pk2(q0.x), wreg[cl][u][0]);
                    fma2(*acc, pk2(q0.y), wreg[cl][u][1]);
                    fma2(*acc, pk2(q1.x), wreg[cl][u][2]);
                    fma2(*acc, pk2(q1.y), wreg[cl][u][3]);
                }
            }
            unsigned long long acc = add2(add2(a0, a1), add2(a2, a3));
            unsigned long long accO = __shfl_down_sync(0xffffffffu, acc, 1);
            if (h == 0) {
                float A0, A1, B0, B1;
                unpk2(acc, A0, A1);
                unpk2(accO, B0, B1);
                u2base[t * 128 + e2a]      = (A0 + B0) * p2;
                u2base[t * 128 + e2a + 16] = (A1 + B1) * p2;
            }
        }
    }
    __syncthreads();

    // ---- Phase C: scan2 (128 threads, pipelined) ----
    if (tid < 128) {
        const int e = tid;
        const float* up = g_u2 + (size_t)n * TT * 128 + e;
        float psp = 0.f, r = 0.f;
        float cur[10], nxt[10];
        #pragma unroll
        for (int k = 0; k < 10; k++) cur[k] = up[k * 128];
        for (int tb = 0; tb < TT; tb += 10) {
            if (tb + 10 < TT) {
                #pragma unroll
                for (int k = 0; k < 10; k++) nxt[k] = up[(tb + 10 + k) * 128];
            }
            #pragma unroll
            for (int k = 0; k < 10; k++) {
                psp = fmaf(DECAY_F, psp, cur[k]);
                float s = (psp - r >= 1.0f) ? 1.0f : 0.0f;
                r = DECAY_F * (r + s);
                s2b[(tb + k) * 128 + e] = (unsigned char)(s != 0.f);
            }
            #pragma unroll
            for (int k = 0; k < 10; k++) cur[k] = nxt[k];
        }
    }
    __syncthreads();

    // ---- Phase D: dense layer, thread = timestep ----
    if (tid < TT) {
        const unsigned char* row = &s2b[tid * 128];
        float o0 = 0.f, o1 = 0.f;
        #pragma unroll 16
        for (int e = 0; e < 128; e++) {
            float s = (float)row[e];
            o0 = fmaf(s, slin[e], o0);
            o1 = fmaf(s, slin[128 + e], o1);
        }
        out[n * 200 + tid * 2]     = o0;
        out[n * 200 + tid * 2 + 1] = o1;
    }
}

// ---------------------------------------------------------------------------
#define FUSED_SMEM (TT * TSTR * 4 + 544 * 4 + 12800)  // 208576 B

extern "C" void kernel_launch(void* const* d_in, const int* in_sizes, int n_in,
                              void* d_out, int out_size) {
    const float* x   = (const float*)d_in[0];  // (64,100,2,32,32)
    const float* w1  = (const float*)d_in[1];  // (4,2,5,5)
    const float* w2  = (const float*)d_in[2];  // (8,4,3,3)
    const float* lin = (const float*)d_in[3];  // (2,8,4,4)
    const float* p1  = (const float*)d_in[4];  // scalar
    const float* p2  = (const float*)d_in[5];  // scalar
    float* out = (float*)d_out;                // (64,100,2)

    cudaFuncSetAttribute(fused_kernel,
                         cudaFuncAttributeMaxDynamicSharedMemorySize, FUSED_SMEM);

    // 4 launches; the 4th (the ncu-captured one) is the fused kernel, so the
    // next profile verifies the bank-conflict fix.
    prep_kernel<<<1, 128>>>(w1);
    conv1_kernel<<<800, 256>>>(x, p1, 0);     // frames    0..3199
    conv1_kernel<<<800, 256>>>(x, p1, 3200);  // frames 3200..6399
    fused_kernel<<<NB, 512, FUSED_SMEM>>>(w2, lin, p2, out);
}

// round 17
// speedup vs baseline: 1.3564x; 1.0291x over previous
#include <cuda_runtime.h>

// ---------------------------------------------------------------------------
// SlayerNet forward:
//   K0 prep  : fold conv1 (5x5 + sumpool4) into effective 8x8/stride-4
//              weights ONCE -> g_w1eff. (Previously re-folded per conv1 block
//              via ~25 serialized global loads = the dominant latency cost.)
//   K1 conv1 (x2 half-grids): x -> conv1eff -> g_u1 [t][n*256+e],
//              4 frames per 256-thread block.
//   K2 fused (512 threads), 4 barrier-separated parallel phases:
//     A: scan1 (PSP+refractory) per element, ALL t -> spike tile in SMEM
//     B: conv2eff for ALL t in parallel (t-stride 4) -> g_u2 (pre-scaled)
//     C: scan2 per element over t -> s2 spike bytes in SMEM
//     D: dense -> out (64,100,2)
//   Fused tile stride = 484 floats (≡4 mod 32 banks) so phase-B threads that
//   differ only in t no longer 4-way bank-conflict (480 ≡ 0 mod 32 did).
// ---------------------------------------------------------------------------

#define TT   100
#define NB   64
#define NE1  16384   // 64 * 256 stage-1 elements (4,8,8)
#define TSTR 484     // fused spike-tile stride in floats (was 480)

// exp(-1/10) rounded to f32 (matches jnp f32 cast of np.exp(-0.1))
#define DECAY_F 0.9048374180359595f

// scratch (device globals: no allocations allowed)
__device__ float  g_u1[TT * NE1];
__device__ float  g_u2[NB * TT * 128];
__device__ float4 g_w1eff[128];   // [ci][u][v] -> (co0,co1,co2,co3)

// ---- packed f32x2 helpers (Blackwell FFMA2 path, PTX-only) ----------------
__device__ __forceinline__ unsigned long long pk2(float x) {
    unsigned int b = __float_as_uint(x);
    unsigned long long r;
    asm("mov.b64 %0, {%1, %1};" : "=l"(r) : "r"(b));
    return r;
}
__device__ __forceinline__ unsigned long long pack2(float lo, float hi) {
    unsigned long long r;
    asm("mov.b64 %0, {%1, %2};" : "=l"(r) : "r"(__float_as_uint(lo)), "r"(__float_as_uint(hi)));
    return r;
}
__device__ __forceinline__ void fma2(unsigned long long& acc,
                                     unsigned long long a,
                                     unsigned long long b) {
    asm("fma.rn.f32x2 %0, %1, %2, %0;" : "+l"(acc) : "l"(a), "l"(b));
}
__device__ __forceinline__ unsigned long long add2(unsigned long long a,
                                                   unsigned long long b) {
    unsigned long long r;
    asm("add.rn.f32x2 %0, %1, %2;" : "=l"(r) : "l"(a), "l"(b));
    return r;
}
__device__ __forceinline__ void unpk2(unsigned long long v, float& lo, float& hi) {
    unsigned int l, h;
    asm("mov.b64 {%0, %1}, %2;" : "=r"(l), "=r"(h) : "l"(v));
    lo = __uint_as_float(l);
    hi = __uint_as_float(h);
}

// ---------------------------------------------------------------------------
// K0: one-block prep — fold conv1+pool into g_w1eff. Arithmetic and summation
// order identical to the previous in-block fold (rel_err 0.0 lineage).
// ---------------------------------------------------------------------------
__global__ void prep_kernel(const float* __restrict__ w1) {
    int i = threadIdx.x;  // 128 threads
    int v = i & 7, u = (i >> 3) & 7, ci = i >> 6;
    int ky0 = max(0, u - 3), ky1 = min(4, u);
    int kx0 = max(0, v - 3), kx1 = min(4, v);
    float acc[4];
    #pragma unroll
    for (int co = 0; co < 4; co++) {
        float s = 0.f;
        for (int ky = ky0; ky <= ky1; ky++)
            for (int kx = kx0; kx <= kx1; kx++)
                s += w1[((co * 2 + ci) * 5 + ky) * 5 + kx];
        acc[co] = s;
    }
    g_w1eff[i] = make_float4(acc[0], acc[1], acc[2], acc[3]);
}

// ---------------------------------------------------------------------------
// K1: conv1eff, 4 frames per 256-thread block. Group g = tid>>6 owns frame
// base + 4*blockIdx.x + g; lid = tid&63 is the pooled-window index. Effective
// weights now LOADED (128 float4, coalesced) instead of re-folded per block.
// Staging, halo fill, compute loop, arithmetic orders unchanged.
// ---------------------------------------------------------------------------
__global__ __launch_bounds__(256) void conv1_kernel(const float* __restrict__ x,
                                                    const float* __restrict__ pool1p,
                                                    int frame_base) {
    __shared__ __align__(16) float sx[4][2 * 36 * 36];  // 4 x 10.4KB
    __shared__ float4 sw[128];
    const int tid = threadIdx.x;
    const int g   = tid >> 6;        // frame group 0..3
    const int lid = tid & 63;        // window index within frame
    const int f = frame_base + blockIdx.x * 4 + g;
    const int n = f / 100, t = f - n * 100;
    float* sxf = sx[g];

    // ---- prefetch this group's frame into registers (8 float4/thread) ----
    const float4* xg = (const float4*)(x + (size_t)f * 2048);
    float4 rx[8];
    #pragma unroll
    for (int k = 0; k < 8; k++) rx[k] = xg[lid + 64 * k];

    // effective weights: one coalesced float4 load per thread (tid<128)
    if (tid < 128) sw[tid] = g_w1eff[tid];

    // halo-only zero fill (disjoint from interior cells written below)
    for (int j = lid; j < 288; j += 64) {
        int ci = j / 144, rr = (j / 36) & 3, col = j % 36;
        int row = (rr < 2) ? rr : 32 + rr;
        sxf[(ci * 36 + row) * 36 + col] = 0.f;
    }
    for (int j = lid; j < 256; j += 64) {
        int ci = j >> 7, r2 = (j >> 2) & 31, cc = j & 3;
        int col = (cc < 2) ? cc : 32 + cc;
        sxf[(ci * 36 + 2 + r2) * 36 + col] = 0.f;
    }

    // ---- stage prefetched frame into the padded tile ----
    #pragma unroll
    for (int k = 0; k < 8; k++) {
        int i4 = lid + 64 * k;
        int ci = i4 >> 8, rem = i4 & 255, y = rem >> 3, xq = rem & 7;
        float* d = &sxf[(ci * 36 + y + 2) * 36 + 4 * xq + 2];
        d[0] = rx[k].x; d[1] = rx[k].y; d[2] = rx[k].z; d[3] = rx[k].w;
    }
    __syncthreads();  // single barrier

    const int px = lid & 7, py = lid >> 3;
    unsigned long long acc01 = 0ull, acc23 = 0ull;
    #pragma unroll
    for (int ci = 0; ci < 2; ci++) {
        #pragma unroll
        for (int u = 0; u < 8; u++) {
            const float* row = &sxf[(ci * 36 + py * 4 + u) * 36 + px * 4];
            float4 r0 = *(const float4*)row;
            float4 r1 = *(const float4*)(row + 4);
            float xv[8] = {r0.x, r0.y, r0.z, r0.w, r1.x, r1.y, r1.z, r1.w};
            #pragma unroll
            for (int v = 0; v < 8; v++) {
                const ulonglong2 w = *(const ulonglong2*)&sw[(ci * 8 + u) * 8 + v];
                unsigned long long xx = pk2(xv[v]);
                fma2(acc01, xx, w.x);
                fma2(acc23, xx, w.y);
            }
        }
    }
    const float p1 = *pool1p;
    float a0, a1, a2, a3;
    unpk2(acc01, a0, a1);
    unpk2(acc23, a2, a3);
    const int ob = t * NE1 + n * 256 + py * 8 + px;  // e = co*64 + py*8 + px
    g_u1[ob]       = a0 * p1;
    g_u1[ob + 64]  = a1 * p1;
    g_u1[ob + 128] = a2 * p1;
    g_u1[ob + 192] = a3 * p1;
}

// ---------------------------------------------------------------------------
// K2: fused, phase-parallel. grid=64 (one block per batch), 512 threads,
// ~204KB dynamic SMEM. Tile stride 484 (bank-spread); otherwise unchanged.
//   SMEM: tile  [100][TSTR] float                               193600 B
//         slin  [256] float                                       1024 B
//         sw2   [288] float                                       1152 B
//         s2b   [100][128] bytes                                 12800 B
// ---------------------------------------------------------------------------
__global__ __launch_bounds__(512) void fused_kernel(const float* __restrict__ w2,
                                                    const float* __restrict__ lin,
                                                    const float* __restrict__ pool2p,
                                                    float* __restrict__ out) {
    extern __shared__ __align__(16) float smem[];
    float* tile = smem;                                   // TT*TSTR floats
    float* slin = smem + TT * TSTR;                       // 256
    float* sw2  = smem + TT * TSTR + 256;                 // 288
    unsigned char* s2b = (unsigned char*)(smem + TT * TSTR + 544);  // 12800 B

    const int tid = threadIdx.x;
    const int n = blockIdx.x;

    for (int i = tid; i < 288; i += 512) sw2[i] = w2[i];
    if (tid < 256) slin[tid] = lin[tid];
    {
        float4* t4 = (float4*)tile;
        for (int i = tid; i < TT * TSTR / 4; i += 512)
            t4[i] = make_float4(0.f, 0.f, 0.f, 0.f);
    }
    __syncthreads();

    // ---- Phase A: scan1 for all t (256 threads, MLP-10 pipelined loads) ----
    if (tid < 256) {
        const int e = tid;
        const int ci = e >> 6, y = (e >> 3) & 7, xx = e & 7;
        const int sofs = (ci * 10 + y + 1) * 12 + xx + 3;
        const float* up = g_u1 + n * 256 + e;

        float psp = 0.f, r = 0.f;
        float cur[10], nxt[10];
        #pragma unroll
        for (int k = 0; k < 10; k++) cur[k] = up[k * NE1];
        for (int tb = 0; tb < TT; tb += 10) {
            if (tb + 10 < TT) {
                #pragma unroll
                for (int k = 0; k < 10; k++) nxt[k] = up[(tb + 10 + k) * NE1];
            }
            #pragma unroll
            for (int k = 0; k < 10; k++) {
                psp = fmaf(DECAY_F, psp, cur[k]);
                float s = (psp - r >= 1.0f) ? 1.0f : 0.0f;
                r = DECAY_F * (r + s);
                tile[(tb + k) * TSTR + sofs] = s;
            }
            #pragma unroll
            for (int k = 0; k < 10; k++) cur[k] = nxt[k];
        }
    }
    __syncthreads();

    // ---- Phase B: conv2eff for all t (512 threads, t-stride 4) ----
    {
        const int tq = tid >> 7;       // 0..3
        const int q  = tid & 127;
        const int h  = q & 1;          // ci half
        const int w  = (q >> 1) & 15;  // window
        const int p  = q >> 5;         // co-pair
        const int py = w >> 2, px = w & 3;

        unsigned long long wreg[2][4][4];
        #pragma unroll
        for (int cl = 0; cl < 2; cl++) {
            int ci = 2 * h + cl;
            #pragma unroll
            for (int u = 0; u < 4; u++) {
                #pragma unroll
                for (int v = 0; v < 4; v++) {
                    int ky0 = max(0, u - 1), ky1 = min(2, u);
                    int kx0 = max(0, v - 1), kx1 = min(2, v);
                    float s0 = 0.f, s1 = 0.f;
                    for (int ky = ky0; ky <= ky1; ky++)
                        for (int kx = kx0; kx <= kx1; kx++) {
                            s0 += sw2[((2 * p)     * 4 + ci) * 9 + ky * 3 + kx];
                            s1 += sw2[((2 * p + 1) * 4 + ci) * 9 + ky * 3 + kx];
                        }
                    wreg[cl][u][v] = pack2(s0, s1);
                }
            }
        }
        const float p2 = *pool2p;
        const int e2a = 32 * p + w;
        const int rofs = (2 * h * 10 + py * 2) * 12 + px * 2 + 2;
        float* u2base = g_u2 + (size_t)n * TT * 128;

        for (int t = tq; t < TT; t += 4) {
            const float* tb = &tile[t * TSTR + rofs];
            unsigned long long a0 = 0ull, a1 = 0ull, a2 = 0ull, a3 = 0ull;
            #pragma unroll
            for (int cl = 0; cl < 2; cl++) {
                #pragma unroll
                for (int u = 0; u < 4; u++) {
                    const float* row = tb + (cl * 10 + u) * 12;
                    float2 q0 = *(const float2*)row;
                    float2 q1 = *(const float2*)(row + 2);
                    unsigned long long* acc =
                        (u == 0) ? &a0 : (u == 1) ? &a1 : (u == 2) ? &a2 : &a3;
                    fma2(*acc, pk2(q0.x), wreg[cl][u][0]);
                    fma2(*acc, pk2(q0.y), wreg[cl][u][1]);
                    fma2(*acc, pk2(q1.x), wreg[cl][u][2]);
                    fma2(*acc, pk2(q1.y), wreg[cl][u][3]);
                }
            }
            unsigned long long acc = add2(add2(a0, a1), add2(a2, a3));
            unsigned long long accO = __shfl_down_sync(0xffffffffu, acc, 1);
            if (h == 0) {
                float A0, A1, B0, B1;
                unpk2(acc, A0, A1);
                unpk2(accO, B0, B1);
                u2base[t * 128 + e2a]      = (A0 + B0) * p2;
                u2base[t * 128 + e2a + 16] = (A1 + B1) * p2;
            }
        }
    }
    __syncthreads();

    // ---- Phase C: scan2 (128 threads, pipelined) ----
    if (tid < 128) {
        const int e = tid;
        const float* up = g_u2 + (size_t)n * TT * 128 + e;
        float psp = 0.f, r = 0.f;
        float cur[10], nxt[10];
        #pragma unroll
        for (int k = 0; k < 10; k++) cur[k] = up[k * 128];
        for (int tb = 0; tb < TT; tb += 10) {
            if (tb + 10 < TT) {
                #pragma unroll
                for (int k = 0; k < 10; k++) nxt[k] = up[(tb + 10 + k) * 128];
            }
            #pragma unroll
            for (int k = 0; k < 10; k++) {
                psp = fmaf(DECAY_F, psp, cur[k]);
                float s = (psp - r >= 1.0f) ? 1.0f : 0.0f;
                r = DECAY_F * (r + s);
                s2b[(tb + k) * 128 + e] = (unsigned char)(s != 0.f);
            }
            #pragma unroll
            for (int k = 0; k < 10; k++) cur[k] = nxt[k];
        }
    }
    __syncthreads();

    // ---- Phase D: dense layer, thread = timestep ----
    if (tid < TT) {
        const unsigned char* row = &s2b[tid * 128];
        float o0 = 0.f, o1 = 0.f;
        #pragma unroll 16
        for (int e = 0; e < 128; e++) {
            float s = (float)row[e];
            o0 = fmaf(s, slin[e], o0);
            o1 = fmaf(s, slin[128 + e], o1);
        }
        out[n * 200 + tid * 2]     = o0;
        out[n * 200 + tid * 2 + 1] = o1;
    }
}

// ---------------------------------------------------------------------------
#define FUSED_SMEM (TT * TSTR * 4 + 544 * 4 + 12800)  // 208576 B

extern "C" void kernel_launch(void* const* d_in, const int* in_sizes, int n_in,
                              void* d_out, int out_size) {
    const float* x   = (const float*)d_in[0];  // (64,100,2,32,32)
    const float* w1  = (const float*)d_in[1];  // (4,2,5,5)
    const float* w2  = (const float*)d_in[2];  // (8,4,3,3)
    const float* lin = (const float*)d_in[3];  // (2,8,4,4)
    const float* p1  = (const float*)d_in[4];  // scalar
    const float* p2  = (const float*)d_in[5];  // scalar
    float* out = (float*)d_out;                // (64,100,2)

    cudaFuncSetAttribute(fused_kernel,
                         cudaFuncAttributeMaxDynamicSharedMemorySize, FUSED_SMEM);

    // 4 launches; the 4th (the ncu-captured one) is the fused kernel, so the
    // next profile verifies the bank-conflict fix.
    prep_kernel<<<1, 128>>>(w1);
    conv1_kernel<<<800, 256>>>(x, p1, 0);     // frames    0..3199
    conv1_kernel<<<800, 256>>>(x, p1, 3200);  // frames 3200..6399
    fused_kernel<<<NB, 512, FUSED_SMEM>>>(w2, lin, p2, out);
}